// round 3
// baseline (speedup 1.0000x reference)
#include <cuda_runtime.h>
#include <cuda_bf16.h>
#include <mma.h>
using namespace nvcuda;

#define T_ 8
#define N_ 1024
#define D_ 128
static constexpr float SCALE = 0.08838834764831845f; // 1/sqrt(128)

// ---- scratch (__device__ globals; no allocation allowed) ----
__device__ __align__(16) __nv_bfloat16 g_Xh[T_ * N_ * D_];        // 2 MB
__device__ __align__(16) unsigned      g_adjp[N_ * (N_ / 32)];    // 128 KB bitmask
__device__ __align__(16) float         g_Y [T_ * N_ * D_];        // 4 MB node features
__device__ __align__(16) float         g_SW[N_ * T_ * T_];        // 256 KB sigmoid weights

// ---------------- K0: fp32 -> bf16 cast ----------------
__global__ void k_cast(const float* __restrict__ x) {
    int i = blockIdx.x * blockDim.x + threadIdx.x;
    if (i < T_ * N_ * D_) g_Xh[i] = __float2bfloat16(x[i]);
}

// ---------------- K0b: pack adj into bitmask ----------------
__global__ void k_pack(const int* __restrict__ adj) {
    int idx = blockIdx.x * blockDim.x + threadIdx.x;   // over N*N
    unsigned m = __ballot_sync(~0u, adj[idx] > 0);
    if ((threadIdx.x & 31) == 0) g_adjp[idx >> 5] = m;
}

// ---------------- K1: fused attention  Y_t = softmax(mask(X X^T * scale)) X ----------------
// One block per (m-tile of 64 rows, timestamp). 256 threads (8 warps).
// No online max needed: scores bounded (~|25| max), exp() safe in fp32,
// masked lanes produce exactly 0 — ratios identical to reference softmax.
//
// smem layout (dynamic, 71936 B):
//   [0      ) Xm   bf16 64x136   17408
//   [17408  ) Xj   bf16 64x136   17408
//   [34816  ) S    f32  64x72    18432
//   [53248  ) P    bf16 64x72     9216
//   [62464  ) rsum f32  64x4      1024
//   [63488  ) adj  u32  64x32     8192
//   [71680  ) linv f32  64         256
//   epilogue: O f32 64x132 = 33792 reuses [0,33792)
#define SM_XJ   17408
#define SM_S    34816
#define SM_P    53248
#define SM_RS   62464
#define SM_ADJ  63488
#define SM_LI   71680
#define SM_TOT  71936

__global__ void k_attn() {
    extern __shared__ char smraw[];
    __nv_bfloat16* Xms  = (__nv_bfloat16*)smraw;
    __nv_bfloat16* Xjs  = (__nv_bfloat16*)(smraw + SM_XJ);
    float*         Ssm  = (float*)(smraw + SM_S);
    __nv_bfloat16* Pts  = (__nv_bfloat16*)(smraw + SM_P);
    float*         rsum = (float*)(smraw + SM_RS);
    unsigned*      adjs = (unsigned*)(smraw + SM_ADJ);
    float*         linv = (float*)(smraw + SM_LI);
    float*         Osm  = (float*)smraw;   // epilogue only

    int t  = blockIdx.y;
    int m0 = blockIdx.x * 64;
    int tid = threadIdx.x;
    int w   = tid >> 5;
    const __nv_bfloat16* Xt = g_Xh + (size_t)t * N_ * D_;

    // load Xm tile + adj bits + zero rsum
    #pragma unroll
    for (int q = 0; q < 4; q++) {
        int idx = tid + q * 256;            // 1024 uint4
        int r = idx >> 4, c = (idx & 15) * 8;
        *(uint4*)&Xms[r * 136 + c] = *(const uint4*)&Xt[(m0 + r) * D_ + c];
    }
    #pragma unroll
    for (int q = 0; q < 8; q++) {
        int i = tid + q * 256;              // 2048 words
        adjs[i] = g_adjp[(m0 + (i >> 5)) * 32 + (i & 31)];
    }
    if (tid < 64) {
        rsum[tid * 4] = 0.f; rsum[tid * 4 + 1] = 0.f;
        rsum[tid * 4 + 2] = 0.f; rsum[tid * 4 + 3] = 0.f;
    }

    // persistent output accumulators: warp tile 32x32, layout 2x4 over 64x128
    int wmO = (w >> 2) * 32, wnO = (w & 3) * 32;
    wmma::fragment<wmma::accumulator, 16, 16, 16, float> o[2][2];
    #pragma unroll
    for (int a = 0; a < 2; a++)
        #pragma unroll
        for (int b = 0; b < 2; b++) wmma::fill_fragment(o[a][b], 0.0f);

    // QK warp tile 32x16, layout 2x4 over 64x64
    int wmS = (w >> 2) * 32, wnS = (w & 3) * 16;

    int er = tid >> 2, ep = tid & 3;        // exp stage: 4 threads / row

    for (int j0 = 0; j0 < N_; j0 += 64) {
        __syncthreads();                    // Xj free (prev AV done), S free
        // load Xj tile
        #pragma unroll
        for (int q = 0; q < 4; q++) {
            int idx = tid + q * 256;
            int r = idx >> 4, c = (idx & 15) * 8;
            *(uint4*)&Xjs[r * 136 + c] = *(const uint4*)&Xt[(j0 + r) * D_ + c];
        }
        __syncthreads();

        // S = Xm . Xj^T  (64x64)
        {
            wmma::fragment<wmma::accumulator, 16, 16, 16, float> accS[2];
            wmma::fill_fragment(accS[0], 0.0f);
            wmma::fill_fragment(accS[1], 0.0f);
            #pragma unroll
            for (int k0 = 0; k0 < 128; k0 += 16) {
                wmma::fragment<wmma::matrix_a, 16, 16, 16, __nv_bfloat16, wmma::row_major> a0, a1;
                wmma::fragment<wmma::matrix_b, 16, 16, 16, __nv_bfloat16, wmma::col_major> b0;
                wmma::load_matrix_sync(a0, &Xms[wmS * 136 + k0], 136);
                wmma::load_matrix_sync(a1, &Xms[(wmS + 16) * 136 + k0], 136);
                wmma::load_matrix_sync(b0, &Xjs[wnS * 136 + k0], 136);
                wmma::mma_sync(accS[0], a0, b0, accS[0]);
                wmma::mma_sync(accS[1], a1, b0, accS[1]);
            }
            wmma::store_matrix_sync(&Ssm[wmS * 72 + wnS], accS[0], 72, wmma::mem_row_major);
            wmma::store_matrix_sync(&Ssm[(wmS + 16) * 72 + wnS], accS[1], 72, wmma::mem_row_major);
        }
        __syncthreads();

        // exp + mask + rowsum -> P (bf16)
        {
            unsigned wb = adjs[er * 32 + (j0 >> 5) + (ep >> 1)] >> ((ep & 1) * 16);
            float part = 0.f;
            const float* srow = &Ssm[er * 72 + ep * 16];
            __nv_bfloat16* prow = &Pts[er * 72 + ep * 16];
            float pv[16];
            #pragma unroll
            for (int cc = 0; cc < 16; cc++) {
                float p = ((wb >> cc) & 1u) ? __expf(srow[cc] * SCALE) : 0.0f;
                pv[cc] = p;
                part += p;
            }
            #pragma unroll
            for (int cc = 0; cc < 16; cc += 2)
                *(__nv_bfloat162*)&prow[cc] = __floats2bfloat162_rn(pv[cc], pv[cc + 1]);
            rsum[er * 4 + ep] += part;
        }
        __syncthreads();

        // O += P . Xj   (64x64 * 64x128)
        #pragma unroll
        for (int kk = 0; kk < 4; kk++) {
            wmma::fragment<wmma::matrix_a, 16, 16, 16, __nv_bfloat16, wmma::row_major> a0, a1;
            wmma::fragment<wmma::matrix_b, 16, 16, 16, __nv_bfloat16, wmma::row_major> b0, b1;
            wmma::load_matrix_sync(a0, &Pts[wmO * 72 + kk * 16], 72);
            wmma::load_matrix_sync(a1, &Pts[(wmO + 16) * 72 + kk * 16], 72);
            wmma::load_matrix_sync(b0, &Xjs[(kk * 16) * 136 + wnO], 136);
            wmma::load_matrix_sync(b1, &Xjs[(kk * 16) * 136 + wnO + 16], 136);
            wmma::mma_sync(o[0][0], a0, b0, o[0][0]);
            wmma::mma_sync(o[0][1], a0, b1, o[0][1]);
            wmma::mma_sync(o[1][0], a1, b0, o[1][0]);
            wmma::mma_sync(o[1][1], a1, b1, o[1][1]);
        }
    }

    // epilogue: 1/l, stage O to smem, normalize, write Y
    __syncthreads();
    if (tid < 64)
        linv[tid] = 1.0f / (rsum[tid * 4] + rsum[tid * 4 + 1] +
                            rsum[tid * 4 + 2] + rsum[tid * 4 + 3]);
    __syncthreads();                        // also: everyone done reading Xm/Xj region
    #pragma unroll
    for (int a = 0; a < 2; a++)
        #pragma unroll
        for (int b = 0; b < 2; b++)
            wmma::store_matrix_sync(&Osm[(wmO + a * 16) * 132 + wnO + b * 16],
                                    o[a][b], 132, wmma::mem_row_major);
    __syncthreads();
    float* Yout = g_Y + ((size_t)t * N_ + m0) * D_;
    #pragma unroll
    for (int q = 0; q < 8; q++) {
        int f4 = tid + q * 256;             // 2048 float4
        int r = f4 >> 5, c4 = (f4 & 31) * 4;
        float inv = linv[r];
        const float* src = &Osm[r * 132 + c4];
        float4 v = make_float4(src[0] * inv, src[1] * inv, src[2] * inv, src[3] * inv);
        *(float4*)&Yout[r * D_ + c4] = v;
    }
}

// ---------------- K2: per node 8x8 Gram + sigmoid (fp32) ----------------
__global__ void k_temp() {
    int gwarp = (blockIdx.x * blockDim.x + threadIdx.x) >> 5;
    int lane  = threadIdx.x & 31;
    if (gwarp >= N_) return;
    int n = gwarp;

    float y[T_][4];
    #pragma unroll
    for (int t = 0; t < T_; t++)
        #pragma unroll
        for (int q = 0; q < 4; q++)
            y[t][q] = g_Y[((size_t)t * N_ + n) * D_ + q * 32 + lane];

    float G[64];
    #pragma unroll
    for (int p = 0; p < 64; p++) G[p] = 0.0f;
    #pragma unroll
    for (int t = 0; t < T_; t++)
        #pragma unroll
        for (int s = 0; s < T_; s++)
            #pragma unroll
            for (int q = 0; q < 4; q++)
                G[t * 8 + s] = fmaf(y[t][q], y[s][q], G[t * 8 + s]);

    #pragma unroll
    for (int p = 0; p < 64; p++) {
        float v = G[p];
        #pragma unroll
        for (int o = 16; o; o >>= 1) v += __shfl_xor_sync(~0u, v, o);
        G[p] = v;
    }

    #pragma unroll
    for (int k = 0; k < 2; k++) {
        int p = lane + k * 32;
        float x = G[p] * SCALE;
        g_SW[n * 64 + p] = 1.0f / (1.0f + __expf(-x));
    }
}

// ---------------- K3: broadcast-expand 256MB write ----------------
// out[s*N + j, t*N + i] = sw[j, t, s]   (independent of i)
__global__ void k_expand(float* __restrict__ out) {
    int r = blockIdx.x;            // 8192 rows
    int s = r >> 10, j = r & 1023;
    int tid = threadIdx.x;         // 256 threads
    float4* orow = (float4*)(out + (size_t)r * 8192);
    #pragma unroll
    for (int t = 0; t < T_; t++) {
        float v = g_SW[j * 64 + t * 8 + s];
        orow[t * 256 + tid] = make_float4(v, v, v, v);
    }
}

extern "C" void kernel_launch(void* const* d_in, const int* in_sizes, int n_in,
                              void* d_out, int out_size) {
    const float* raw = (const float*)d_in[0];
    const int*   adj = (const int*)d_in[1];
    float*       out = (float*)d_out;

    static bool attr_set = false;
    if (!attr_set) {
        cudaFuncSetAttribute(k_attn, cudaFuncAttributeMaxDynamicSharedMemorySize, SM_TOT);
        attr_set = true;
    }

    k_cast<<<(T_ * N_ * D_ + 255) / 256, 256>>>(raw);
    k_pack<<<(N_ * N_) / 256, 256>>>(adj);
    k_attn<<<dim3(16, T_), 256, SM_TOT>>>();
    k_temp<<<N_ / 8, 256>>>();
    k_expand<<<T_ * N_, 256>>>(out);
}

// round 4
// speedup vs baseline: 1.3856x; 1.3856x over previous
#include <cuda_runtime.h>
#include <cuda_bf16.h>
#include <mma.h>
using namespace nvcuda;

#define T_ 8
#define N_ 1024
#define D_ 128
#define JC_ 4                    // j-chunks (split-K of the attention j loop)
static constexpr float SCALE = 0.08838834764831845f; // 1/sqrt(128)

// ---- scratch (__device__ globals; no allocation allowed) ----
__device__ __align__(16) __nv_bfloat16 g_Xh[T_ * N_ * D_];            // 2 MB
__device__ __align__(16) unsigned      g_adjp[N_ * (N_ / 32)];        // 128 KB bitmask
__device__ __align__(16) float         g_Opart[JC_ * T_ * N_ * D_];   // 16 MB partial numerators
__device__ __align__(16) float         g_lpart[JC_ * T_ * N_];        // 128 KB partial denominators
__device__ __align__(16) float         g_Y [T_ * N_ * D_];            // 4 MB node features
__device__ __align__(16) float         g_SW[N_ * T_ * T_];            // 256 KB sigmoid weights

// ---------------- K0: fp32 -> bf16 cast ----------------
__global__ void k_cast(const float* __restrict__ x) {
    int i = blockIdx.x * blockDim.x + threadIdx.x;
    if (i < T_ * N_ * D_) g_Xh[i] = __float2bfloat16(x[i]);
}

// ---------------- K0b: pack adj into bitmask ----------------
__global__ void k_pack(const int* __restrict__ adj) {
    int idx = blockIdx.x * blockDim.x + threadIdx.x;   // over N*N
    unsigned m = __ballot_sync(~0u, adj[idx] > 0);
    if ((threadIdx.x & 31) == 0) g_adjp[idx >> 5] = m;
}

// ---------------- K1a: fused partial attention ----------------
// grid (16 m-tiles, 4 j-chunks, 8 t), 256 threads. Each block:
//   Opart = sum_{j in chunk} exp(mask(Xm.Xj^T * scale)) . Xj   (64x128 f32)
//   lpart = row sums of the exp terms.
// No online max needed: scores bounded (|s|<~25), exp safe in fp32,
// masked entries exactly 0 -> ratios identical to reference softmax.
//
// smem (dynamic, 65792 B):
//   [0      ) Xm   bf16 64x136   17408
//   [17408  ) Xj   bf16 64x136   17408
//   [34816  ) S    f32  64x72    18432
//   [53248  ) P    bf16 64x72     9216
//   [62464  ) rsum f32  64x4      1024
//   [63488  ) adj  u32  64x8      2048
//   epilogue: O f32 64x132 = 33792 reuses [0,33792)
#define SM_XJ   17408
#define SM_S    34816
#define SM_P    53248
#define SM_RS   62464
#define SM_ADJ  63488
#define SM_TOT  65536

__global__ void k_attn() {
    extern __shared__ char smraw[];
    __nv_bfloat16* Xms  = (__nv_bfloat16*)smraw;
    __nv_bfloat16* Xjs  = (__nv_bfloat16*)(smraw + SM_XJ);
    float*         Ssm  = (float*)(smraw + SM_S);
    __nv_bfloat16* Pts  = (__nv_bfloat16*)(smraw + SM_P);
    float*         rsum = (float*)(smraw + SM_RS);
    unsigned*      adjs = (unsigned*)(smraw + SM_ADJ);
    float*         Osm  = (float*)smraw;   // epilogue only

    int m0 = blockIdx.x * 64;
    int jc = blockIdx.y;
    int t  = blockIdx.z;
    int jbase = jc * (N_ / JC_);           // 256-wide chunk
    int tid = threadIdx.x;
    int w   = tid >> 5;
    const __nv_bfloat16* Xt = g_Xh + (size_t)t * N_ * D_;

    // load Xm tile + adj bits (8 words/row for this chunk) + zero rsum
    #pragma unroll
    for (int q = 0; q < 4; q++) {
        int idx = tid + q * 256;            // 1024 uint4
        int r = idx >> 4, c = (idx & 15) * 8;
        *(uint4*)&Xms[r * 136 + c] = *(const uint4*)&Xt[(m0 + r) * D_ + c];
    }
    #pragma unroll
    for (int q = 0; q < 2; q++) {
        int i = tid + q * 256;              // 512 words
        adjs[i] = g_adjp[(m0 + (i >> 3)) * 32 + jc * 8 + (i & 7)];
    }
    if (tid < 64) {
        rsum[tid * 4] = 0.f; rsum[tid * 4 + 1] = 0.f;
        rsum[tid * 4 + 2] = 0.f; rsum[tid * 4 + 3] = 0.f;
    }

    // persistent output accumulators: warp tile 32x32, layout 2x4 over 64x128
    int wmO = (w >> 2) * 32, wnO = (w & 3) * 32;
    wmma::fragment<wmma::accumulator, 16, 16, 16, float> o[2][2];
    #pragma unroll
    for (int a = 0; a < 2; a++)
        #pragma unroll
        for (int b = 0; b < 2; b++) wmma::fill_fragment(o[a][b], 0.0f);

    // QK warp tile 32x16, layout 2x4 over 64x64
    int wmS = (w >> 2) * 32, wnS = (w & 3) * 16;
    int er = tid >> 2, ep = tid & 3;        // exp stage: 4 threads / row

    #pragma unroll
    for (int it = 0; it < (N_ / JC_) / 64; it++) {   // 4 iterations
        int j0 = jbase + it * 64;
        __syncthreads();                    // Xj/S free (prev AV done)
        #pragma unroll
        for (int q = 0; q < 4; q++) {
            int idx = tid + q * 256;
            int r = idx >> 4, c = (idx & 15) * 8;
            *(uint4*)&Xjs[r * 136 + c] = *(const uint4*)&Xt[(j0 + r) * D_ + c];
        }
        __syncthreads();

        // S = Xm . Xj^T (64x64)
        {
            wmma::fragment<wmma::accumulator, 16, 16, 16, float> accS[2];
            wmma::fill_fragment(accS[0], 0.0f);
            wmma::fill_fragment(accS[1], 0.0f);
            #pragma unroll
            for (int k0 = 0; k0 < 128; k0 += 16) {
                wmma::fragment<wmma::matrix_a, 16, 16, 16, __nv_bfloat16, wmma::row_major> a0, a1;
                wmma::fragment<wmma::matrix_b, 16, 16, 16, __nv_bfloat16, wmma::col_major> b0;
                wmma::load_matrix_sync(a0, &Xms[wmS * 136 + k0], 136);
                wmma::load_matrix_sync(a1, &Xms[(wmS + 16) * 136 + k0], 136);
                wmma::load_matrix_sync(b0, &Xjs[wnS * 136 + k0], 136);
                wmma::mma_sync(accS[0], a0, b0, accS[0]);
                wmma::mma_sync(accS[1], a1, b0, accS[1]);
            }
            wmma::store_matrix_sync(&Ssm[wmS * 72 + wnS], accS[0], 72, wmma::mem_row_major);
            wmma::store_matrix_sync(&Ssm[(wmS + 16) * 72 + wnS], accS[1], 72, wmma::mem_row_major);
        }
        __syncthreads();

        // exp + mask + rowsum -> P (bf16)
        {
            unsigned wb = adjs[er * 8 + it * 2 + (ep >> 1)] >> ((ep & 1) * 16);
            float part = 0.f;
            const float* srow = &Ssm[er * 72 + ep * 16];
            __nv_bfloat16* prow = &Pts[er * 72 + ep * 16];
            float pv[16];
            #pragma unroll
            for (int cc = 0; cc < 16; cc++) {
                float p = ((wb >> cc) & 1u) ? __expf(srow[cc] * SCALE) : 0.0f;
                pv[cc] = p;
                part += p;
            }
            #pragma unroll
            for (int cc = 0; cc < 16; cc += 2)
                *(__nv_bfloat162*)&prow[cc] = __floats2bfloat162_rn(pv[cc], pv[cc + 1]);
            rsum[er * 4 + ep] += part;
        }
        __syncthreads();

        // O += P . Xj  (64x64 * 64x128)
        #pragma unroll
        for (int kk = 0; kk < 4; kk++) {
            wmma::fragment<wmma::matrix_a, 16, 16, 16, __nv_bfloat16, wmma::row_major> a0, a1;
            wmma::fragment<wmma::matrix_b, 16, 16, 16, __nv_bfloat16, wmma::row_major> b0, b1;
            wmma::load_matrix_sync(a0, &Pts[wmO * 72 + kk * 16], 72);
            wmma::load_matrix_sync(a1, &Pts[(wmO + 16) * 72 + kk * 16], 72);
            wmma::load_matrix_sync(b0, &Xjs[(kk * 16) * 136 + wnO], 136);
            wmma::load_matrix_sync(b1, &Xjs[(kk * 16) * 136 + wnO + 16], 136);
            wmma::mma_sync(o[0][0], a0, b0, o[0][0]);
            wmma::mma_sync(o[0][1], a0, b1, o[0][1]);
            wmma::mma_sync(o[1][0], a1, b0, o[1][0]);
            wmma::mma_sync(o[1][1], a1, b1, o[1][1]);
        }
    }

    // epilogue: write lpart, stage O to smem, write Opart (no normalize here)
    __syncthreads();                        // all AV reads of Xjs done; rsum final
    if (tid < 64)
        g_lpart[(jc * T_ + t) * N_ + m0 + tid] =
            rsum[tid * 4] + rsum[tid * 4 + 1] + rsum[tid * 4 + 2] + rsum[tid * 4 + 3];
    #pragma unroll
    for (int a = 0; a < 2; a++)
        #pragma unroll
        for (int b = 0; b < 2; b++)
            wmma::store_matrix_sync(&Osm[(wmO + a * 16) * 132 + wnO + b * 16],
                                    o[a][b], 132, wmma::mem_row_major);
    __syncthreads();
    float* Oout = g_Opart + (((size_t)jc * T_ + t) * N_ + m0) * D_;
    #pragma unroll
    for (int q = 0; q < 8; q++) {
        int f4 = tid + q * 256;             // 2048 float4
        int r = f4 >> 5, c4 = (f4 & 31) * 4;
        const float* src = &Osm[r * 132 + c4];
        *(float4*)&Oout[r * D_ + c4] = make_float4(src[0], src[1], src[2], src[3]);
    }
}

// ---------------- K1b: reduce partials + normalize -> Y ----------------
__global__ void k_reduce() {
    int i4 = blockIdx.x * blockDim.x + threadIdx.x;   // over TND/4 float4
    if (i4 >= T_ * N_ * D_ / 4) return;
    int row = i4 >> 5;                                // global (t*N + n) row
    float l = g_lpart[row] + g_lpart[T_ * N_ + row] +
              g_lpart[2 * T_ * N_ + row] + g_lpart[3 * T_ * N_ + row];
    float inv = 1.0f / l;
    float4 a = ((const float4*)g_Opart)[i4];
    float4 b = ((const float4*)g_Opart)[i4 + (T_ * N_ * D_ / 4)];
    float4 c = ((const float4*)g_Opart)[i4 + 2 * (T_ * N_ * D_ / 4)];
    float4 d = ((const float4*)g_Opart)[i4 + 3 * (T_ * N_ * D_ / 4)];
    float4 r;
    r.x = (a.x + b.x + c.x + d.x) * inv;
    r.y = (a.y + b.y + c.y + d.y) * inv;
    r.z = (a.z + b.z + c.z + d.z) * inv;
    r.w = (a.w + b.w + c.w + d.w) * inv;
    ((float4*)g_Y)[i4] = r;
}

// ---------------- K2: per node 8x8 Gram + sigmoid (smem, no shuffles) ----------------
// block = 256 threads = 4 nodes x 64 threads; thread (t,s) does a 128-dot from smem.
__global__ void k_temp() {
    __shared__ float ysm[4][T_][132];       // padded stride: conflict-free float4
    int tid = threadIdx.x;
    int nb  = blockIdx.x * 4;

    // load 4 nodes x 8 t x 128 d = 1024 float4; each thread 4 float4
    #pragma unroll
    for (int q = 0; q < 4; q++) {
        int idx = tid + q * 256;            // 0..1023
        int node = idx >> 8;                // /256: 32 float4 per (node,t)... no:
        // per node: 8 rows x 32 float4 = 256 float4 -> node = idx>>8, rem = idx&255
        int rem = idx & 255;
        int tt = rem >> 5, d4 = (rem & 31) * 4;
        float4 v = *(const float4*)&g_Y[(((size_t)tt * N_) + nb + node) * D_ + d4];
        *(float4*)&ysm[node][tt][d4] = v;
    }
    __syncthreads();

    int node = tid >> 6;                    // 4 nodes
    int p    = tid & 63;
    int tt   = p >> 3, ss = p & 7;
    const float* yt = ysm[node][tt];
    const float* ys = ysm[node][ss];
    float acc = 0.f;
    #pragma unroll
    for (int d4 = 0; d4 < 128; d4 += 4) {
        float4 a = *(const float4*)&yt[d4];
        float4 b = *(const float4*)&ys[d4];
        acc = fmaf(a.x, b.x, acc); acc = fmaf(a.y, b.y, acc);
        acc = fmaf(a.z, b.z, acc); acc = fmaf(a.w, b.w, acc);
    }
    float x = acc * SCALE;
    g_SW[(nb + node) * 64 + p] = 1.0f / (1.0f + __expf(-x));
}

// ---------------- K3: broadcast-expand 256MB write ----------------
// out[s*N + j, t*N + i] = sw[j, t, s]   (independent of i)
__global__ void k_expand(float* __restrict__ out) {
    int r = blockIdx.x;            // 8192 rows
    int s = r >> 10, j = r & 1023;
    int tid = threadIdx.x;         // 256 threads
    float4* orow = (float4*)(out + (size_t)r * 8192);
    #pragma unroll
    for (int t = 0; t < T_; t++) {
        float v = g_SW[j * 64 + t * 8 + s];
        orow[t * 256 + tid] = make_float4(v, v, v, v);
    }
}

extern "C" void kernel_launch(void* const* d_in, const int* in_sizes, int n_in,
                              void* d_out, int out_size) {
    const float* raw = (const float*)d_in[0];
    const int*   adj = (const int*)d_in[1];
    float*       out = (float*)d_out;

    static bool attr_set = false;
    if (!attr_set) {
        cudaFuncSetAttribute(k_attn, cudaFuncAttributeMaxDynamicSharedMemorySize, SM_TOT);
        attr_set = true;
    }

    k_cast<<<(T_ * N_ * D_ + 255) / 256, 256>>>(raw);
    k_pack<<<(N_ * N_) / 256, 256>>>(adj);
    k_attn<<<dim3(16, JC_, T_), 256, SM_TOT>>>();
    k_reduce<<<(T_ * N_ * D_ / 4 + 255) / 256, 256>>>();
    k_temp<<<N_ / 4, 256>>>();
    k_expand<<<T_ * N_, 256>>>(out);
}

// round 7
// speedup vs baseline: 1.4422x; 1.0408x over previous
#include <cuda_runtime.h>
#include <cuda_bf16.h>
#include <mma.h>
using namespace nvcuda;

#define T_ 8
#define N_ 1024
#define D_ 128
#define JC_ 4                    // j-chunks (split-K of the attention j loop)
static constexpr float SCALE = 0.08838834764831845f; // 1/sqrt(128)

// ---- scratch (__device__ globals; no allocation allowed) ----
__device__ __align__(16) __nv_bfloat16 g_Xh[T_ * N_ * D_];            // 2 MB
__device__ __align__(16) unsigned      g_adjp[N_ * (N_ / 32)];        // 128 KB bitmask
__device__ __align__(16) float         g_Opart[JC_ * T_ * N_ * D_];   // 16 MB partial numerators
__device__ __align__(16) float         g_lpart[JC_ * T_ * N_];        // 128 KB partial denominators
__device__ __align__(16) float         g_SW[N_ * T_ * T_];            // 256 KB sigmoid weights

// ---------------- K0: fp32 -> bf16 cast ----------------
__global__ void k_cast(const float* __restrict__ x) {
    int i = blockIdx.x * blockDim.x + threadIdx.x;
    if (i < T_ * N_ * D_) g_Xh[i] = __float2bfloat16(x[i]);
}

// ---------------- K0b: pack adj into bitmask ----------------
__global__ void k_pack(const int* __restrict__ adj) {
    int idx = blockIdx.x * blockDim.x + threadIdx.x;   // over N*N
    unsigned m = __ballot_sync(~0u, adj[idx] > 0);
    if ((threadIdx.x & 31) == 0) g_adjp[idx >> 5] = m;
}

// ---------------- K1: fused partial attention (ROUND-4 PROVEN) ----------------
// grid (16 m-tiles, 4 j-chunks, 8 t), 256 threads. Each block:
//   Opart = sum_{j in chunk} exp(mask(Xm.Xj^T * scale)) . Xj   (64x128 f32)
//   lpart = row sums of the exp terms.
// No online max needed: scores bounded (|s|<~25), exp safe in fp32,
// masked entries exactly 0 -> ratios identical to reference softmax.
#define SM_XJ   17408
#define SM_S    34816
#define SM_P    53248
#define SM_RS   62464
#define SM_ADJ  63488
#define SM_TOT  65536

__global__ void k_attn() {
    extern __shared__ char smraw[];
    __nv_bfloat16* Xms  = (__nv_bfloat16*)smraw;
    __nv_bfloat16* Xjs  = (__nv_bfloat16*)(smraw + SM_XJ);
    float*         Ssm  = (float*)(smraw + SM_S);
    __nv_bfloat16* Pts  = (__nv_bfloat16*)(smraw + SM_P);
    float*         rsum = (float*)(smraw + SM_RS);
    unsigned*      adjs = (unsigned*)(smraw + SM_ADJ);
    float*         Osm  = (float*)smraw;   // epilogue only

    int m0 = blockIdx.x * 64;
    int jc = blockIdx.y;
    int t  = blockIdx.z;
    int jbase = jc * (N_ / JC_);           // 256-wide chunk
    int tid = threadIdx.x;
    int w   = tid >> 5;
    const __nv_bfloat16* Xt = g_Xh + (size_t)t * N_ * D_;

    // load Xm tile + adj bits (8 words/row for this chunk) + zero rsum
    #pragma unroll
    for (int q = 0; q < 4; q++) {
        int idx = tid + q * 256;            // 1024 uint4
        int r = idx >> 4, c = (idx & 15) * 8;
        *(uint4*)&Xms[r * 136 + c] = *(const uint4*)&Xt[(m0 + r) * D_ + c];
    }
    #pragma unroll
    for (int q = 0; q < 2; q++) {
        int i = tid + q * 256;              // 512 words
        adjs[i] = g_adjp[(m0 + (i >> 3)) * 32 + jc * 8 + (i & 7)];
    }
    if (tid < 64) {
        rsum[tid * 4] = 0.f; rsum[tid * 4 + 1] = 0.f;
        rsum[tid * 4 + 2] = 0.f; rsum[tid * 4 + 3] = 0.f;
    }

    // persistent output accumulators: warp tile 32x32, layout 2x4 over 64x128
    int wmO = (w >> 2) * 32, wnO = (w & 3) * 32;
    wmma::fragment<wmma::accumulator, 16, 16, 16, float> o[2][2];
    #pragma unroll
    for (int a = 0; a < 2; a++)
        #pragma unroll
        for (int b = 0; b < 2; b++) wmma::fill_fragment(o[a][b], 0.0f);

    // QK warp tile 32x16, layout 2x4 over 64x64
    int wmS = (w >> 2) * 32, wnS = (w & 3) * 16;
    int er = tid >> 2, ep = tid & 3;        // exp stage: 4 threads / row

    #pragma unroll
    for (int it = 0; it < (N_ / JC_) / 64; it++) {   // 4 iterations
        int j0 = jbase + it * 64;
        __syncthreads();                    // Xj/S free (prev AV done)
        #pragma unroll
        for (int q = 0; q < 4; q++) {
            int idx = tid + q * 256;
            int r = idx >> 4, c = (idx & 15) * 8;
            *(uint4*)&Xjs[r * 136 + c] = *(const uint4*)&Xt[(j0 + r) * D_ + c];
        }
        __syncthreads();

        // S = Xm . Xj^T (64x64)
        {
            wmma::fragment<wmma::accumulator, 16, 16, 16, float> accS[2];
            wmma::fill_fragment(accS[0], 0.0f);
            wmma::fill_fragment(accS[1], 0.0f);
            #pragma unroll
            for (int k0 = 0; k0 < 128; k0 += 16) {
                wmma::fragment<wmma::matrix_a, 16, 16, 16, __nv_bfloat16, wmma::row_major> a0, a1;
                wmma::fragment<wmma::matrix_b, 16, 16, 16, __nv_bfloat16, wmma::col_major> b0;
                wmma::load_matrix_sync(a0, &Xms[wmS * 136 + k0], 136);
                wmma::load_matrix_sync(a1, &Xms[(wmS + 16) * 136 + k0], 136);
                wmma::load_matrix_sync(b0, &Xjs[wnS * 136 + k0], 136);
                wmma::mma_sync(accS[0], a0, b0, accS[0]);
                wmma::mma_sync(accS[1], a1, b0, accS[1]);
            }
            wmma::store_matrix_sync(&Ssm[wmS * 72 + wnS], accS[0], 72, wmma::mem_row_major);
            wmma::store_matrix_sync(&Ssm[(wmS + 16) * 72 + wnS], accS[1], 72, wmma::mem_row_major);
        }
        __syncthreads();

        // exp + mask + rowsum -> P (bf16)
        {
            unsigned wb = adjs[er * 8 + it * 2 + (ep >> 1)] >> ((ep & 1) * 16);
            float part = 0.f;
            const float* srow = &Ssm[er * 72 + ep * 16];
            __nv_bfloat16* prow = &Pts[er * 72 + ep * 16];
            float pv[16];
            #pragma unroll
            for (int cc = 0; cc < 16; cc++) {
                float p = ((wb >> cc) & 1u) ? __expf(srow[cc] * SCALE) : 0.0f;
                pv[cc] = p;
                part += p;
            }
            #pragma unroll
            for (int cc = 0; cc < 16; cc += 2)
                *(__nv_bfloat162*)&prow[cc] = __floats2bfloat162_rn(pv[cc], pv[cc + 1]);
            rsum[er * 4 + ep] += part;
        }
        __syncthreads();

        // O += P . Xj  (64x64 * 64x128)
        #pragma unroll
        for (int kk = 0; kk < 4; kk++) {
            wmma::fragment<wmma::matrix_a, 16, 16, 16, __nv_bfloat16, wmma::row_major> a0, a1;
            wmma::fragment<wmma::matrix_b, 16, 16, 16, __nv_bfloat16, wmma::row_major> b0, b1;
            wmma::load_matrix_sync(a0, &Pts[wmO * 72 + kk * 16], 72);
            wmma::load_matrix_sync(a1, &Pts[(wmO + 16) * 72 + kk * 16], 72);
            wmma::load_matrix_sync(b0, &Xjs[(kk * 16) * 136 + wnO], 136);
            wmma::load_matrix_sync(b1, &Xjs[(kk * 16) * 136 + wnO + 16], 136);
            wmma::mma_sync(o[0][0], a0, b0, o[0][0]);
            wmma::mma_sync(o[0][1], a0, b1, o[0][1]);
            wmma::mma_sync(o[1][0], a1, b0, o[1][0]);
            wmma::mma_sync(o[1][1], a1, b1, o[1][1]);
        }
    }

    // epilogue: write lpart, stage O to smem, write Opart (no normalize here)
    __syncthreads();                        // all AV reads of Xjs done; rsum final
    if (tid < 64)
        g_lpart[(jc * T_ + t) * N_ + m0 + tid] =
            rsum[tid * 4] + rsum[tid * 4 + 1] + rsum[tid * 4 + 2] + rsum[tid * 4 + 3];
    #pragma unroll
    for (int a = 0; a < 2; a++)
        #pragma unroll
        for (int b = 0; b < 2; b++)
            wmma::store_matrix_sync(&Osm[(wmO + a * 16) * 132 + wnO + b * 16],
                                    o[a][b], 132, wmma::mem_row_major);
    __syncthreads();
    float* Oout = g_Opart + (((size_t)jc * T_ + t) * N_ + m0) * D_;
    #pragma unroll
    for (int q = 0; q < 8; q++) {
        int f4 = tid + q * 256;             // 2048 float4
        int r = f4 >> 5, c4 = (f4 & 31) * 4;
        const float* src = &Osm[r * 132 + c4];
        *(float4*)&Oout[r * D_ + c4] = make_float4(src[0], src[1], src[2], src[3]);
    }
}

// ---------------- K2: fused reduce+normalize+Gram+sigmoid ----------------
// block = 256 threads = 4 nodes; sums the JC_ partial-O chunks into smem,
// computes per-(t,s) 128-dots, scales by 1/(l_t l_s) and sigmoids.
__global__ void k_temp() {
    __shared__ float ysm[4][T_][132];       // raw numerator sums, padded
    __shared__ float linv_s[32];            // [node][t]
    int tid = threadIdx.x;
    int nb4 = blockIdx.x * 4;

    if (tid < 32) {
        int node = tid >> 3, tt = tid & 7;
        int row = tt * N_ + nb4 + node;
        float l = 0.f;
        #pragma unroll
        for (int c = 0; c < JC_; c++) l += g_lpart[c * T_ * N_ + row];
        // guard: semantically inert on valid data (l > 0 always);
        // converts upstream failures into finite diagnosable error, not NaN.
        linv_s[tid] = (l > 0.f) ? (1.0f / l) : 0.0f;
    }

    #pragma unroll
    for (int q = 0; q < 4; q++) {
        int idx = tid + q * 256;            // 1024 positions
        int node = idx >> 8;
        int rem = idx & 255;
        int tt = rem >> 5, d4 = (rem & 31) * 4;
        size_t base = (((size_t)tt * N_) + nb4 + node) * D_ + d4;
        float4 acc = *(const float4*)&g_Opart[base];
        #pragma unroll
        for (int c = 1; c < JC_; c++) {
            float4 v = *(const float4*)&g_Opart[(size_t)c * T_ * N_ * D_ + base];
            acc.x += v.x; acc.y += v.y; acc.z += v.z; acc.w += v.w;
        }
        *(float4*)&ysm[node][tt][d4] = acc;
    }
    __syncthreads();

    int node = tid >> 6;
    int p    = tid & 63;
    int tt   = p >> 3, ss = p & 7;
    const float* yt = ysm[node][tt];
    const float* ys = ysm[node][ss];
    float acc = 0.f;
    #pragma unroll
    for (int d4 = 0; d4 < 128; d4 += 4) {
        float4 a = *(const float4*)&yt[d4];
        float4 b = *(const float4*)&ys[d4];
        acc = fmaf(a.x, b.x, acc); acc = fmaf(a.y, b.y, acc);
        acc = fmaf(a.z, b.z, acc); acc = fmaf(a.w, b.w, acc);
    }
    float x = acc * linv_s[node * 8 + tt] * linv_s[node * 8 + ss] * SCALE;
    g_SW[(nb4 + node) * 64 + p] = 1.0f / (1.0f + __expf(-x));
}

// ---------------- K3: broadcast-expand 256MB write ----------------
// out[s*N + j, t*N + i] = sw[j, t, s]   (independent of i)
__global__ void k_expand(float* __restrict__ out) {
    int r = blockIdx.x;            // 8192 rows
    int s = r >> 10, j = r & 1023;
    int tid = threadIdx.x;         // 256 threads
    float4* orow = (float4*)(out + (size_t)r * 8192);
    #pragma unroll
    for (int t = 0; t < T_; t++) {
        float v = g_SW[j * 64 + t * 8 + s];
        orow[t * 256 + tid] = make_float4(v, v, v, v);
    }
}

extern "C" void kernel_launch(void* const* d_in, const int* in_sizes, int n_in,
                              void* d_out, int out_size) {
    const float* raw = (const float*)d_in[0];
    const int*   adj = (const int*)d_in[1];
    float*       out = (float*)d_out;

    static bool attr_set = false;
    if (!attr_set) {
        cudaFuncSetAttribute(k_attn, cudaFuncAttributeMaxDynamicSharedMemorySize, SM_TOT);
        attr_set = true;
    }

    k_cast<<<(T_ * N_ * D_ + 255) / 256, 256>>>(raw);
    k_pack<<<(N_ * N_) / 256, 256>>>(adj);
    k_attn<<<dim3(16, JC_, T_), 256, SM_TOT>>>();
    k_temp<<<N_ / 4, 256>>>();
    k_expand<<<T_ * N_, 256>>>(out);
}

// round 8
// speedup vs baseline: 1.4660x; 1.0165x over previous
#include <cuda_runtime.h>
#include <cuda_bf16.h>
#include <mma.h>
#include <cstdint>
using namespace nvcuda;

#define T_ 8
#define N_ 1024
#define D_ 128
#define JC_ 4                    // j-chunks (split of the attention j loop)
static constexpr float SCALE = 0.08838834764831845f; // 1/sqrt(128)

// ---- scratch (__device__ globals; no allocation allowed) ----
__device__ __align__(16) __nv_bfloat16 g_Xh[T_ * N_ * D_];            // 2 MB
__device__ __align__(16) unsigned      g_adjp[N_ * (N_ / 32)];        // 128 KB bitmask
__device__ __align__(16) float         g_Opart[JC_ * T_ * N_ * D_];   // 16 MB partial numerators
__device__ __align__(16) float         g_lpart[JC_ * T_ * N_];        // 128 KB partial denominators

// ---------------- PTX helpers ----------------
__device__ __forceinline__ uint32_t smaddr(const void* p) {
    return (uint32_t)__cvta_generic_to_shared(p);
}
__device__ __forceinline__ void cpa16(uint32_t dst, const void* src) {
    asm volatile("cp.async.cg.shared.global [%0], [%1], 16;" :: "r"(dst), "l"(src));
}
__device__ __forceinline__ void cpa_commit() { asm volatile("cp.async.commit_group;"); }
template <int NN> __device__ __forceinline__ void cpa_wait() {
    asm volatile("cp.async.wait_group %0;" :: "n"(NN));
}
__device__ __forceinline__ void ldsm4(uint32_t& r0, uint32_t& r1, uint32_t& r2, uint32_t& r3,
                                      uint32_t a) {
    asm volatile("ldmatrix.sync.aligned.m8n8.x4.shared.b16 {%0,%1,%2,%3},[%4];"
                 : "=r"(r0), "=r"(r1), "=r"(r2), "=r"(r3) : "r"(a));
}
__device__ __forceinline__ void mma16816(float* c, uint32_t a0, uint32_t a1, uint32_t a2,
                                         uint32_t a3, uint32_t b0, uint32_t b1) {
    asm volatile("mma.sync.aligned.m16n8k16.row.col.f32.bf16.bf16.f32 "
                 "{%0,%1,%2,%3}, {%4,%5,%6,%7}, {%8,%9}, {%0,%1,%2,%3};"
                 : "+f"(c[0]), "+f"(c[1]), "+f"(c[2]), "+f"(c[3])
                 : "r"(a0), "r"(a1), "r"(a2), "r"(a3), "r"(b0), "r"(b1));
}

// ---------------- K0: fp32 -> bf16 cast ----------------
__global__ void k_cast(const float* __restrict__ x) {
    int i = blockIdx.x * blockDim.x + threadIdx.x;
    if (i < T_ * N_ * D_) g_Xh[i] = __float2bfloat16(x[i]);
}

// ---------------- K0b: pack adj into bitmask ----------------
__global__ void k_pack(const int* __restrict__ adj) {
    int idx = blockIdx.x * blockDim.x + threadIdx.x;   // over N*N
    unsigned m = __ballot_sync(~0u, adj[idx] > 0);
    if ((threadIdx.x & 31) == 0) g_adjp[idx >> 5] = m;
}

// ---------------- K1: fused partial attention (hybrid, fixed fills) ----------------
// grid (16 m-tiles, JC_ j-chunks, T_), 128 threads (4 warps).
// QK: raw mma.m16n8k16, S in registers; mask+exp in registers; P -> smem at
// explicit documented C-fragment coordinates. AV: R4-proven wmma path with
// persistent accumulators (warp w owns output cols [32w, 32w+32)).
// Xj is cp.async double-buffered; EVERY Xj fill loop covers 1024 uint4
// (64 rows x 16 uint4) — the R5/R6 failure was q<4 covering only rows 0-31.
// smem layout (63488 B):
//   [0      ) Xm  bf16 64x136  17408
//   [17408  ) Xj0 bf16 64x136  17408
//   [34816  ) Xj1 bf16 64x136  17408
//   [52224  ) P   bf16 64x72    9216
//   [61440  ) adj u32 64x8      2048
//   epilogue: O f32 64x132 = 33792 reuses [0,33792)
#define SM_XJ0  17408
#define SM_XJ1  34816
#define SM_P    52224
#define SM_ADJ  61440
#define SM_TOT  63488

__global__ void __launch_bounds__(128, 3) k_attn() {
    extern __shared__ char smraw[];
    __nv_bfloat16* Xms  = (__nv_bfloat16*)smraw;
    __nv_bfloat16* Xj0  = (__nv_bfloat16*)(smraw + SM_XJ0);
    __nv_bfloat16* Xj1  = (__nv_bfloat16*)(smraw + SM_XJ1);
    __nv_bfloat16* Pts  = (__nv_bfloat16*)(smraw + SM_P);
    unsigned*      adjs = (unsigned*)(smraw + SM_ADJ);
    float*         Osm  = (float*)smraw;    // epilogue only
    uint32_t smXm  = smaddr(smraw);
    uint32_t smXj0 = smXm + SM_XJ0;
    uint32_t smXj1 = smXm + SM_XJ1;

    int m0 = blockIdx.x * 64;
    int jc = blockIdx.y;
    int t  = blockIdx.z;
    int jbase = jc * (N_ / JC_);            // 256-wide chunk
    int tid = threadIdx.x;
    int w    = tid >> 5;
    int lane = tid & 31;
    const __nv_bfloat16* Xt = g_Xh + (size_t)t * N_ * D_;

    // ---- issue cp.async for j-tile 0 FIRST (overlap with Xm fill) ----
    #pragma unroll
    for (int q = 0; q < 8; q++) {           // 1024 uint4 = full 64x128 tile
        int idx = tid + q * 128;
        int r = idx >> 4, c = (idx & 15) * 8;
        cpa16(smXj0 + (uint32_t)(r * 136 + c) * 2, &Xt[(jbase + r) * D_ + c]);
    }
    cpa_commit();

    // ---- load Xm tile (plain) + adj bits ----
    #pragma unroll
    for (int q = 0; q < 8; q++) {
        int idx = tid + q * 128;            // 1024 uint4
        int r = idx >> 4, c = (idx & 15) * 8;
        *(uint4*)&Xms[r * 136 + c] = *(const uint4*)&Xt[(m0 + r) * D_ + c];
    }
    #pragma unroll
    for (int q = 0; q < 4; q++) {
        int i = tid + q * 128;              // 512 words
        adjs[i] = g_adjp[(m0 + (i >> 3)) * 32 + jc * 8 + (i & 7)];
    }

    // ---- per-thread fragment constants (documented mma layouts) ----
    int gr = lane >> 2, tc = lane & 3;      // C-frag: rows gr/gr+8, cols 2tc/2tc+1
    int lrow  = lane & 15;
    int lcol8 = 8 * (lane >> 4);
    uint32_t aoffA    = (uint32_t)((16 * w + lrow) * 136 + lcol8) * 2;  // + k0*2
    uint32_t aoffBrow = (uint32_t)(lrow * 136 + lcol8) * 2;             // + (16p*136+k0)*2

    // persistent AV accumulators: warp w -> O[0:64, 32w:32w+32)
    wmma::fragment<wmma::accumulator, 16, 16, 16, float> oacc[4][2];
    #pragma unroll
    for (int a = 0; a < 4; a++)
        #pragma unroll
        for (int b = 0; b < 2; b++) wmma::fill_fragment(oacc[a][b], 0.0f);

    float rs0 = 0.f, rs1 = 0.f;
    const int NIT = (N_ / JC_) / 64;        // 4 j-tiles per chunk

    #pragma unroll 1
    for (int it = 0; it < NIT; it++) {
        uint32_t XJ = (it & 1) ? smXj1 : smXj0;
        __nv_bfloat16* XJp = (it & 1) ? Xj1 : Xj0;
        if (it + 1 < NIT) {                 // prefetch next into other buffer
            uint32_t XJn = (it & 1) ? smXj0 : smXj1;
            int j0n = jbase + (it + 1) * 64;
            #pragma unroll
            for (int q = 0; q < 8; q++) {   // FULL 1024 uint4 (bug fix)
                int idx = tid + q * 128;
                int r = idx >> 4, c = (idx & 15) * 8;
                cpa16(XJn + (uint32_t)(r * 136 + c) * 2, &Xt[(j0n + r) * D_ + c]);
            }
            cpa_commit();
            cpa_wait<1>();                  // current tile complete
        } else {
            cpa_wait<0>();
        }
        __syncthreads();                    // XJ ready; P free (prev AV done)

        // ---- QK: S(16x64) = Xm_w . Xj^T in registers ----
        float s[8][4];
        #pragma unroll
        for (int nb = 0; nb < 8; nb++)
            #pragma unroll
            for (int k = 0; k < 4; k++) s[nb][k] = 0.0f;

        #pragma unroll
        for (int ks = 0; ks < 8; ks++) {
            int k0 = ks * 16;
            uint32_t a0, a1, a2, a3;
            ldsm4(a0, a1, a2, a3, smXm + aoffA + (uint32_t)k0 * 2);
            #pragma unroll
            for (int p = 0; p < 4; p++) {
                uint32_t q0, q1, q2, q3;
                ldsm4(q0, q1, q2, q3, XJ + aoffBrow + (uint32_t)(16 * p * 136 + k0) * 2);
                mma16816(s[2 * p],     a0, a1, a2, a3, q0, q2);
                mma16816(s[2 * p + 1], a0, a1, a2, a3, q1, q3);
            }
        }

        // ---- mask + exp + rowsum; P -> smem at explicit coordinates ----
        {
            int rowE = 16 * w + gr;
            int ar0 = rowE * 8 + it * 2;
            int ar1 = (rowE + 8) * 8 + it * 2;
            unsigned w0a = adjs[ar0], w0b = adjs[ar0 + 1];
            unsigned w1a = adjs[ar1], w1b = adjs[ar1 + 1];
            #pragma unroll
            for (int nb = 0; nb < 8; nb++) {
                int col = 8 * nb + 2 * tc;              // j col within 64-tile
                unsigned wa = (nb < 4) ? w0a : w0b;
                unsigned wb = (nb < 4) ? w1a : w1b;
                int sh = col & 31;
                // clamp never binds on valid data (s*SCALE <= ~20)
                float e0 = ((wa >> sh) & 1u)       ? __expf(fminf(s[nb][0] * SCALE, 30.f)) : 0.f;
                float e1 = ((wa >> (sh + 1)) & 1u) ? __expf(fminf(s[nb][1] * SCALE, 30.f)) : 0.f;
                float f0 = ((wb >> sh) & 1u)       ? __expf(fminf(s[nb][2] * SCALE, 30.f)) : 0.f;
                float f1 = ((wb >> (sh + 1)) & 1u) ? __expf(fminf(s[nb][3] * SCALE, 30.f)) : 0.f;
                rs0 += e0 + e1;
                rs1 += f0 + f1;
                *(__nv_bfloat162*)&Pts[rowE * 72 + col]       = __floats2bfloat162_rn(e0, e1);
                *(__nv_bfloat162*)&Pts[(rowE + 8) * 72 + col] = __floats2bfloat162_rn(f0, f1);
            }
        }
        __syncthreads();                    // P complete for all 64 rows

        // ---- AV (R4-proven wmma): O[:, 32w:+32] += P . Xj ----
        #pragma unroll
        for (int kk = 0; kk < 4; kk++) {
            wmma::fragment<wmma::matrix_b, 16, 16, 16, __nv_bfloat16, wmma::row_major> b0, b1;
            wmma::load_matrix_sync(b0, &XJp[(kk * 16) * 136 + 32 * w], 136);
            wmma::load_matrix_sync(b1, &XJp[(kk * 16) * 136 + 32 * w + 16], 136);
            #pragma unroll
            for (int rr = 0; rr < 4; rr++) {
                wmma::fragment<wmma::matrix_a, 16, 16, 16, __nv_bfloat16, wmma::row_major> af;
                wmma::load_matrix_sync(af, &Pts[(16 * rr) * 72 + kk * 16], 72);
                wmma::mma_sync(oacc[rr][0], af, b0, oacc[rr][0]);
                wmma::mma_sync(oacc[rr][1], af, b1, oacc[rr][1]);
            }
        }
        __syncthreads();                    // P & XJ fully consumed
    }

    // ---- epilogue: row sums + raw partial O ----
    rs0 += __shfl_xor_sync(~0u, rs0, 1); rs0 += __shfl_xor_sync(~0u, rs0, 2);
    rs1 += __shfl_xor_sync(~0u, rs1, 1); rs1 += __shfl_xor_sync(~0u, rs1, 2);
    if (tc == 0) {
        int lbase = (jc * T_ + t) * N_ + m0;
        g_lpart[lbase + 16 * w + gr]     = rs0;
        g_lpart[lbase + 16 * w + gr + 8] = rs1;
    }
    #pragma unroll
    for (int rr = 0; rr < 4; rr++)
        #pragma unroll
        for (int cc = 0; cc < 2; cc++)
            wmma::store_matrix_sync(&Osm[(16 * rr) * 132 + 32 * w + 16 * cc],
                                    oacc[rr][cc], 132, wmma::mem_row_major);
    __syncthreads();
    float* Oout = g_Opart + ((size_t)(jc * T_ + t) * N_ + m0) * D_;
    #pragma unroll
    for (int q = 0; q < 16; q++) {
        int f4 = tid + q * 128;             // 2048 float4
        int r = f4 >> 5, c4 = (f4 & 31) * 4;
        const float* src = &Osm[r * 132 + c4];
        *(float4*)&Oout[r * D_ + c4] = make_float4(src[0], src[1], src[2], src[3]);
    }
}

// ---------------- K2: fused reduce+normalize+Gram+sigmoid+EXPAND ----------------
// 512 blocks x 256 threads, 2 nodes per block. Sums the JC_ partial-O chunks
// into smem, computes the 8x8 Gram per node, sigmoids, then writes the 256MB
// broadcast output directly (rows s*N+j, 4KB segments per (t,s)).
__global__ void k_tempx(float* __restrict__ out) {
    __shared__ float ysm[2][T_][132];       // raw numerator sums, padded
    __shared__ float linv_s[16];            // [node][t]
    __shared__ float swv[2][64];            // sigmoid weights
    int tid = threadIdx.x;
    int nb2 = blockIdx.x * 2;

    if (tid < 16) {
        int node = tid >> 3, tt = tid & 7;
        int row = tt * N_ + nb2 + node;
        float l = 0.f;
        #pragma unroll
        for (int c = 0; c < JC_; c++) l += g_lpart[c * T_ * N_ + row];
        linv_s[tid] = (l > 0.f) ? (1.0f / l) : 0.0f;   // inert guard
    }

    #pragma unroll
    for (int q = 0; q < 2; q++) {
        int idx = tid + q * 256;            // 512 positions = 2 nodes x 8t x 32 f4
        int node = idx >> 8;
        int rem = idx & 255;
        int tt = rem >> 5, d4 = (rem & 31) * 4;
        size_t base = (((size_t)tt * N_) + nb2 + node) * D_ + d4;
        float4 acc = *(const float4*)&g_Opart[base];
        #pragma unroll
        for (int c = 1; c < JC_; c++) {
            float4 v = *(const float4*)&g_Opart[(size_t)c * T_ * N_ * D_ + base];
            acc.x += v.x; acc.y += v.y; acc.z += v.z; acc.w += v.w;
        }
        *(float4*)&ysm[node][tt][d4] = acc;
    }
    __syncthreads();

    if (tid < 128) {
        int node = tid >> 6;
        int p    = tid & 63;
        int tt   = p >> 3, ss = p & 7;
        const float* yt = ysm[node][tt];
        const float* ys = ysm[node][ss];
        float acc = 0.f;
        #pragma unroll
        for (int d4 = 0; d4 < 128; d4 += 4) {
            float4 a = *(const float4*)&yt[d4];
            float4 b = *(const float4*)&ys[d4];
            acc = fmaf(a.x, b.x, acc); acc = fmaf(a.y, b.y, acc);
            acc = fmaf(a.z, b.z, acc); acc = fmaf(a.w, b.w, acc);
        }
        float x = acc * linv_s[node * 8 + tt] * linv_s[node * 8 + ss] * SCALE;
        swv[node][p] = 1.0f / (1.0f + __expf(-x));
    }
    __syncthreads();

    // expand: out[s*N + j, t*N + i] = swv (independent of i)
    float4* out4 = (float4*)out;
    #pragma unroll 1
    for (int seg = 0; seg < 128; seg++) {
        int node = seg >> 6, t = (seg >> 3) & 7, s = seg & 7;
        float v = swv[node][t * 8 + s];
        size_t row = (size_t)s * N_ + nb2 + node;
        out4[row * 2048 + t * 256 + tid] = make_float4(v, v, v, v);
    }
}

extern "C" void kernel_launch(void* const* d_in, const int* in_sizes, int n_in,
                              void* d_out, int out_size) {
    const float* raw = (const float*)d_in[0];
    const int*   adj = (const int*)d_in[1];
    float*       out = (float*)d_out;

    static bool attr_set = false;
    if (!attr_set) {
        cudaFuncSetAttribute(k_attn, cudaFuncAttributeMaxDynamicSharedMemorySize, SM_TOT);
        attr_set = true;
    }

    k_cast<<<(T_ * N_ * D_ + 255) / 256, 256>>>(raw);
    k_pack<<<(N_ * N_) / 256, 256>>>(adj);
    k_attn<<<dim3(16, JC_, T_), 128, SM_TOT>>>();
    k_tempx<<<N_ / 2, 256>>>(out);
}

// round 10
// speedup vs baseline: 1.5748x; 1.0742x over previous
#include <cuda_runtime.h>
#include <cuda_bf16.h>
#include <mma.h>
#include <cstdint>
using namespace nvcuda;

#define T_ 8
#define N_ 1024
#define D_ 128
#define JC_ 4                    // j-chunks (split of the attention j loop)
static constexpr float SCALE = 0.08838834764831845f; // 1/sqrt(128)

// ---- scratch (__device__ globals; no allocation allowed) ----
__device__ __align__(16) __nv_bfloat16 g_Xh[T_ * N_ * D_];            // 2 MB
__device__ __align__(16) unsigned      g_adjp[N_ * (N_ / 32)];        // 128 KB bitmask
__device__ __align__(16) float         g_Opart[JC_ * T_ * N_ * D_];   // 16 MB partial numerators
__device__ __align__(16) float         g_lpart[JC_ * T_ * N_];        // 128 KB partial denominators

// ---------------- PTX helpers ----------------
__device__ __forceinline__ uint32_t smaddr(const void* p) {
    return (uint32_t)__cvta_generic_to_shared(p);
}
__device__ __forceinline__ void cpa16(uint32_t dst, const void* src) {
    asm volatile("cp.async.cg.shared.global [%0], [%1], 16;" :: "r"(dst), "l"(src));
}
__device__ __forceinline__ void cpa_commit() { asm volatile("cp.async.commit_group;"); }
template <int NN> __device__ __forceinline__ void cpa_wait() {
    asm volatile("cp.async.wait_group %0;" :: "n"(NN));
}
__device__ __forceinline__ void ldsm4(uint32_t& r0, uint32_t& r1, uint32_t& r2, uint32_t& r3,
                                      uint32_t a) {
    asm volatile("ldmatrix.sync.aligned.m8n8.x4.shared.b16 {%0,%1,%2,%3},[%4];"
                 : "=r"(r0), "=r"(r1), "=r"(r2), "=r"(r3) : "r"(a));
}
__device__ __forceinline__ void mma16816(float* c, uint32_t a0, uint32_t a1, uint32_t a2,
                                         uint32_t a3, uint32_t b0, uint32_t b1) {
    asm volatile("mma.sync.aligned.m16n8k16.row.col.f32.bf16.bf16.f32 "
                 "{%0,%1,%2,%3}, {%4,%5,%6,%7}, {%8,%9}, {%0,%1,%2,%3};"
                 : "+f"(c[0]), "+f"(c[1]), "+f"(c[2]), "+f"(c[3])
                 : "r"(a0), "r"(a1), "r"(a2), "r"(a3), "r"(b0), "r"(b1));
}

// ---------------- K0: fp32 -> bf16 cast ----------------
__global__ void k_cast(const float* __restrict__ x) {
    int i = blockIdx.x * blockDim.x + threadIdx.x;
    if (i < T_ * N_ * D_) g_Xh[i] = __float2bfloat16(x[i]);
}

// ---------------- K0b: pack adj into bitmask ----------------
__global__ void k_pack(const int* __restrict__ adj) {
    int idx = blockIdx.x * blockDim.x + threadIdx.x;   // over N*N
    unsigned m = __ballot_sync(~0u, adj[idx] > 0);
    if ((threadIdx.x & 31) == 0) g_adjp[idx >> 5] = m;
}

// ---------------- K1: fused partial attention (R8 proven, unchanged) ----------------
#define SM_XJ0  17408
#define SM_XJ1  34816
#define SM_P    52224
#define SM_ADJ  61440
#define SM_TOT  63488

__global__ void __launch_bounds__(128, 3) k_attn() {
    extern __shared__ char smraw[];
    __nv_bfloat16* Xms  = (__nv_bfloat16*)smraw;
    __nv_bfloat16* Xj0  = (__nv_bfloat16*)(smraw + SM_XJ0);
    __nv_bfloat16* Xj1  = (__nv_bfloat16*)(smraw + SM_XJ1);
    __nv_bfloat16* Pts  = (__nv_bfloat16*)(smraw + SM_P);
    unsigned*      adjs = (unsigned*)(smraw + SM_ADJ);
    float*         Osm  = (float*)smraw;    // epilogue only
    uint32_t smXm  = smaddr(smraw);
    uint32_t smXj0 = smXm + SM_XJ0;
    uint32_t smXj1 = smXm + SM_XJ1;

    int m0 = blockIdx.x * 64;
    int jc = blockIdx.y;
    int t  = blockIdx.z;
    int jbase = jc * (N_ / JC_);            // 256-wide chunk
    int tid = threadIdx.x;
    int w    = tid >> 5;
    int lane = tid & 31;
    const __nv_bfloat16* Xt = g_Xh + (size_t)t * N_ * D_;

    // ---- issue cp.async for j-tile 0 FIRST (overlap with Xm fill) ----
    #pragma unroll
    for (int q = 0; q < 8; q++) {           // 1024 uint4 = full 64x128 tile
        int idx = tid + q * 128;
        int r = idx >> 4, c = (idx & 15) * 8;
        cpa16(smXj0 + (uint32_t)(r * 136 + c) * 2, &Xt[(jbase + r) * D_ + c]);
    }
    cpa_commit();

    // ---- load Xm tile (plain) + adj bits ----
    #pragma unroll
    for (int q = 0; q < 8; q++) {
        int idx = tid + q * 128;            // 1024 uint4
        int r = idx >> 4, c = (idx & 15) * 8;
        *(uint4*)&Xms[r * 136 + c] = *(const uint4*)&Xt[(m0 + r) * D_ + c];
    }
    #pragma unroll
    for (int q = 0; q < 4; q++) {
        int i = tid + q * 128;              // 512 words
        adjs[i] = g_adjp[(m0 + (i >> 3)) * 32 + jc * 8 + (i & 7)];
    }

    // ---- per-thread fragment constants ----
    int gr = lane >> 2, tc = lane & 3;      // C-frag: rows gr/gr+8, cols 2tc/2tc+1
    int lrow  = lane & 15;
    int lcol8 = 8 * (lane >> 4);
    uint32_t aoffA    = (uint32_t)((16 * w + lrow) * 136 + lcol8) * 2;
    uint32_t aoffBrow = (uint32_t)(lrow * 136 + lcol8) * 2;

    wmma::fragment<wmma::accumulator, 16, 16, 16, float> oacc[4][2];
    #pragma unroll
    for (int a = 0; a < 4; a++)
        #pragma unroll
        for (int b = 0; b < 2; b++) wmma::fill_fragment(oacc[a][b], 0.0f);

    float rs0 = 0.f, rs1 = 0.f;
    const int NIT = (N_ / JC_) / 64;        // 4 j-tiles per chunk

    #pragma unroll 1
    for (int it = 0; it < NIT; it++) {
        uint32_t XJ = (it & 1) ? smXj1 : smXj0;
        __nv_bfloat16* XJp = (it & 1) ? Xj1 : Xj0;
        if (it + 1 < NIT) {
            uint32_t XJn = (it & 1) ? smXj0 : smXj1;
            int j0n = jbase + (it + 1) * 64;
            #pragma unroll
            for (int q = 0; q < 8; q++) {   // FULL 1024 uint4
                int idx = tid + q * 128;
                int r = idx >> 4, c = (idx & 15) * 8;
                cpa16(XJn + (uint32_t)(r * 136 + c) * 2, &Xt[(j0n + r) * D_ + c]);
            }
            cpa_commit();
            cpa_wait<1>();
        } else {
            cpa_wait<0>();
        }
        __syncthreads();

        // ---- QK: S(16x64) in registers ----
        float s[8][4];
        #pragma unroll
        for (int nb = 0; nb < 8; nb++)
            #pragma unroll
            for (int k = 0; k < 4; k++) s[nb][k] = 0.0f;

        #pragma unroll
        for (int ks = 0; ks < 8; ks++) {
            int k0 = ks * 16;
            uint32_t a0, a1, a2, a3;
            ldsm4(a0, a1, a2, a3, smXm + aoffA + (uint32_t)k0 * 2);
            #pragma unroll
            for (int p = 0; p < 4; p++) {
                uint32_t q0, q1, q2, q3;
                ldsm4(q0, q1, q2, q3, XJ + aoffBrow + (uint32_t)(16 * p * 136 + k0) * 2);
                mma16816(s[2 * p],     a0, a1, a2, a3, q0, q2);
                mma16816(s[2 * p + 1], a0, a1, a2, a3, q1, q3);
            }
        }

        // ---- mask + exp + rowsum; P -> smem ----
        {
            int rowE = 16 * w + gr;
            int ar0 = rowE * 8 + it * 2;
            int ar1 = (rowE + 8) * 8 + it * 2;
            unsigned w0a = adjs[ar0], w0b = adjs[ar0 + 1];
            unsigned w1a = adjs[ar1], w1b = adjs[ar1 + 1];
            #pragma unroll
            for (int nb = 0; nb < 8; nb++) {
                int col = 8 * nb + 2 * tc;
                unsigned wa = (nb < 4) ? w0a : w0b;
                unsigned wb = (nb < 4) ? w1a : w1b;
                int sh = col & 31;
                float e0 = ((wa >> sh) & 1u)       ? __expf(fminf(s[nb][0] * SCALE, 30.f)) : 0.f;
                float e1 = ((wa >> (sh + 1)) & 1u) ? __expf(fminf(s[nb][1] * SCALE, 30.f)) : 0.f;
                float f0 = ((wb >> sh) & 1u)       ? __expf(fminf(s[nb][2] * SCALE, 30.f)) : 0.f;
                float f1 = ((wb >> (sh + 1)) & 1u) ? __expf(fminf(s[nb][3] * SCALE, 30.f)) : 0.f;
                rs0 += e0 + e1;
                rs1 += f0 + f1;
                *(__nv_bfloat162*)&Pts[rowE * 72 + col]       = __floats2bfloat162_rn(e0, e1);
                *(__nv_bfloat162*)&Pts[(rowE + 8) * 72 + col] = __floats2bfloat162_rn(f0, f1);
            }
        }
        __syncthreads();

        // ---- AV: O[:, 32w:+32] += P . Xj ----
        #pragma unroll
        for (int kk = 0; kk < 4; kk++) {
            wmma::fragment<wmma::matrix_b, 16, 16, 16, __nv_bfloat16, wmma::row_major> b0, b1;
            wmma::load_matrix_sync(b0, &XJp[(kk * 16) * 136 + 32 * w], 136);
            wmma::load_matrix_sync(b1, &XJp[(kk * 16) * 136 + 32 * w + 16], 136);
            #pragma unroll
            for (int rr = 0; rr < 4; rr++) {
                wmma::fragment<wmma::matrix_a, 16, 16, 16, __nv_bfloat16, wmma::row_major> af;
                wmma::load_matrix_sync(af, &Pts[(16 * rr) * 72 + kk * 16], 72);
                wmma::mma_sync(oacc[rr][0], af, b0, oacc[rr][0]);
                wmma::mma_sync(oacc[rr][1], af, b1, oacc[rr][1]);
            }
        }
        __syncthreads();
    }

    // ---- epilogue ----
    rs0 += __shfl_xor_sync(~0u, rs0, 1); rs0 += __shfl_xor_sync(~0u, rs0, 2);
    rs1 += __shfl_xor_sync(~0u, rs1, 1); rs1 += __shfl_xor_sync(~0u, rs1, 2);
    if (tc == 0) {
        int lbase = (jc * T_ + t) * N_ + m0;
        g_lpart[lbase + 16 * w + gr]     = rs0;
        g_lpart[lbase + 16 * w + gr + 8] = rs1;
    }
    #pragma unroll
    for (int rr = 0; rr < 4; rr++)
        #pragma unroll
        for (int cc = 0; cc < 2; cc++)
            wmma::store_matrix_sync(&Osm[(16 * rr) * 132 + 32 * w + 16 * cc],
                                    oacc[rr][cc], 132, wmma::mem_row_major);
    __syncthreads();
    float* Oout = g_Opart + ((size_t)(jc * T_ + t) * N_ + m0) * D_;
    #pragma unroll
    for (int q = 0; q < 16; q++) {
        int f4 = tid + q * 128;             // 2048 float4
        int r = f4 >> 5, c4 = (f4 & 31) * 4;
        const float* src = &Osm[r * 132 + c4];
        __stcs((float4*)&Oout[r * D_ + c4], make_float4(src[0], src[1], src[2], src[3]));
    }
}

// ---------------- K2: fused reduce+Gram+sigmoid+EXPAND (streaming) ----------------
// 1024 blocks x 256 threads, ONE node per block.
// Phase 1: sum JC_ partial-O chunks (streaming __ldcs) + 1/l.
// Phase 2: 8x8 Gram + sigmoid -> swv (64 floats, smem).
// Phase 3: expand — per output row (s fixed), the 8 t-segments are contiguous:
//          each block streams 8 rows x 32KB with pointer-increment arithmetic
//          and __stcs (write-once data, bypass L2 retention).
__global__ void __launch_bounds__(256, 4) k_tempx(float* __restrict__ out) {
    __shared__ float ysm[T_][132];          // raw numerator sums, padded
    __shared__ float linv_s[8];             // [t]
    __shared__ float swv[64];               // sigmoid weights [t][s]
    int tid = threadIdx.x;
    int j   = blockIdx.x;                   // node

    if (tid < 8) {
        int row = tid * N_ + j;
        float l = 0.f;
        #pragma unroll
        for (int c = 0; c < JC_; c++) l += g_lpart[c * T_ * N_ + row];
        linv_s[tid] = (l > 0.f) ? (1.0f / l) : 0.0f;   // inert guard
    }

    // 8t x 32 float4 = 256 positions; one per thread
    {
        int tt = tid >> 5, d4 = (tid & 31) * 4;
        size_t base = (((size_t)tt * N_) + j) * D_ + d4;
        float4 acc = __ldcs((const float4*)&g_Opart[base]);
        #pragma unroll
        for (int c = 1; c < JC_; c++) {
            float4 v = __ldcs((const float4*)&g_Opart[(size_t)c * T_ * N_ * D_ + base]);
            acc.x += v.x; acc.y += v.y; acc.z += v.z; acc.w += v.w;
        }
        *(float4*)&ysm[tt][d4] = acc;
    }
    __syncthreads();

    if (tid < 64) {
        int tt = tid >> 3, ss = tid & 7;
        const float* yt = ysm[tt];
        const float* ys = ysm[ss];
        float acc = 0.f;
        #pragma unroll
        for (int d4 = 0; d4 < 128; d4 += 4) {
            float4 a = *(const float4*)&yt[d4];
            float4 b = *(const float4*)&ys[d4];
            acc = fmaf(a.x, b.x, acc); acc = fmaf(a.y, b.y, acc);
            acc = fmaf(a.z, b.z, acc); acc = fmaf(a.w, b.w, acc);
        }
        float x = acc * linv_s[tt] * linv_s[ss] * SCALE;
        swv[tid] = 1.0f / (1.0f + __expf(-x));          // swv[t*8+s]
    }
    __syncthreads();

    // expand: out[s*N + j, t*N + i] = swv[t*8+s]  (independent of i)
    // per s: one contiguous 32KB row, t-inner, pointer increments only
    #pragma unroll 1
    for (int s = 0; s < T_; s++) {
        float4* p = (float4*)out + ((size_t)s * N_ + j) * 2048 + tid;
        #pragma unroll
        for (int t = 0; t < T_; t++) {
            float v = swv[t * 8 + s];
            __stcs(p, make_float4(v, v, v, v));
            p += 256;
        }
    }
}

extern "C" void kernel_launch(void* const* d_in, const int* in_sizes, int n_in,
                              void* d_out, int out_size) {
    const float* raw = (const float*)d_in[0];
    const int*   adj = (const int*)d_in[1];
    float*       out = (float*)d_out;

    static bool attr_set = false;
    if (!attr_set) {
        cudaFuncSetAttribute(k_attn, cudaFuncAttributeMaxDynamicSharedMemorySize, SM_TOT);
        attr_set = true;
    }

    k_cast<<<(T_ * N_ * D_ + 255) / 256, 256>>>(raw);
    k_pack<<<(N_ * N_) / 256, 256>>>(adj);
    k_attn<<<dim3(16, JC_, T_), 128, SM_TOT>>>();
    k_tempx<<<N_, 256>>>(out);
}

// round 11
// speedup vs baseline: 1.6261x; 1.0326x over previous
#include <cuda_runtime.h>
#include <cuda_bf16.h>
#include <mma.h>
#include <cstdint>
using namespace nvcuda;

#define T_ 8
#define N_ 1024
#define D_ 128
#define JC_ 4                    // j-chunks (split of the attention j loop)
static constexpr float SCALE = 0.08838834764831845f; // 1/sqrt(128)

// ---- scratch (__device__ globals; no allocation allowed) ----
__device__ __align__(16) __nv_bfloat16 g_Xh[T_ * N_ * D_];            // 2 MB
__device__ __align__(16) unsigned      g_adjp[N_ * (N_ / 32)];        // 128 KB bitmask
__device__ __align__(16) float         g_Opart[JC_ * T_ * N_ * D_];   // 16 MB partial numerators
__device__ __align__(16) float         g_lpart[JC_ * T_ * N_];        // 128 KB partial denominators
__device__ __align__(16) float         g_SW[N_ * T_ * T_];            // 256 KB sigmoid weights

// ---------------- PTX helpers ----------------
__device__ __forceinline__ uint32_t smaddr(const void* p) {
    return (uint32_t)__cvta_generic_to_shared(p);
}
__device__ __forceinline__ void cpa16(uint32_t dst, const void* src) {
    asm volatile("cp.async.cg.shared.global [%0], [%1], 16;" :: "r"(dst), "l"(src));
}
__device__ __forceinline__ void cpa_commit() { asm volatile("cp.async.commit_group;"); }
template <int NN> __device__ __forceinline__ void cpa_wait() {
    asm volatile("cp.async.wait_group %0;" :: "n"(NN));
}
__device__ __forceinline__ void ldsm4(uint32_t& r0, uint32_t& r1, uint32_t& r2, uint32_t& r3,
                                      uint32_t a) {
    asm volatile("ldmatrix.sync.aligned.m8n8.x4.shared.b16 {%0,%1,%2,%3},[%4];"
                 : "=r"(r0), "=r"(r1), "=r"(r2), "=r"(r3) : "r"(a));
}
__device__ __forceinline__ void mma16816(float* c, uint32_t a0, uint32_t a1, uint32_t a2,
                                         uint32_t a3, uint32_t b0, uint32_t b1) {
    asm volatile("mma.sync.aligned.m16n8k16.row.col.f32.bf16.bf16.f32 "
                 "{%0,%1,%2,%3}, {%4,%5,%6,%7}, {%8,%9}, {%0,%1,%2,%3};"
                 : "+f"(c[0]), "+f"(c[1]), "+f"(c[2]), "+f"(c[3])
                 : "r"(a0), "r"(a1), "r"(a2), "r"(a3), "r"(b0), "r"(b1));
}

// ---------------- K0: fp32 -> bf16 cast ----------------
__global__ void k_cast(const float* __restrict__ x) {
    int i = blockIdx.x * blockDim.x + threadIdx.x;
    if (i < T_ * N_ * D_) g_Xh[i] = __float2bfloat16(x[i]);
}

// ---------------- K0b: pack adj into bitmask ----------------
__global__ void k_pack(const int* __restrict__ adj) {
    int idx = blockIdx.x * blockDim.x + threadIdx.x;   // over N*N
    unsigned m = __ballot_sync(~0u, adj[idx] > 0);
    if ((threadIdx.x & 31) == 0) g_adjp[idx >> 5] = m;
}

// ---------------- K1: fused partial attention (R8/R10 proven, unchanged) ----------------
#define SM_XJ0  17408
#define SM_XJ1  34816
#define SM_P    52224
#define SM_ADJ  61440
#define SM_TOT  63488

__global__ void __launch_bounds__(128, 3) k_attn() {
    extern __shared__ char smraw[];
    __nv_bfloat16* Xms  = (__nv_bfloat16*)smraw;
    __nv_bfloat16* Xj0  = (__nv_bfloat16*)(smraw + SM_XJ0);
    __nv_bfloat16* Xj1  = (__nv_bfloat16*)(smraw + SM_XJ1);
    __nv_bfloat16* Pts  = (__nv_bfloat16*)(smraw + SM_P);
    unsigned*      adjs = (unsigned*)(smraw + SM_ADJ);
    float*         Osm  = (float*)smraw;    // epilogue only
    uint32_t smXm  = smaddr(smraw);
    uint32_t smXj0 = smXm + SM_XJ0;
    uint32_t smXj1 = smXm + SM_XJ1;

    int m0 = blockIdx.x * 64;
    int jc = blockIdx.y;
    int t  = blockIdx.z;
    int jbase = jc * (N_ / JC_);            // 256-wide chunk
    int tid = threadIdx.x;
    int w    = tid >> 5;
    int lane = tid & 31;
    const __nv_bfloat16* Xt = g_Xh + (size_t)t * N_ * D_;

    // ---- issue cp.async for j-tile 0 FIRST (overlap with Xm fill) ----
    #pragma unroll
    for (int q = 0; q < 8; q++) {           // 1024 uint4 = full 64x128 tile
        int idx = tid + q * 128;
        int r = idx >> 4, c = (idx & 15) * 8;
        cpa16(smXj0 + (uint32_t)(r * 136 + c) * 2, &Xt[(jbase + r) * D_ + c]);
    }
    cpa_commit();

    // ---- load Xm tile (plain) + adj bits ----
    #pragma unroll
    for (int q = 0; q < 8; q++) {
        int idx = tid + q * 128;            // 1024 uint4
        int r = idx >> 4, c = (idx & 15) * 8;
        *(uint4*)&Xms[r * 136 + c] = *(const uint4*)&Xt[(m0 + r) * D_ + c];
    }
    #pragma unroll
    for (int q = 0; q < 4; q++) {
        int i = tid + q * 128;              // 512 words
        adjs[i] = g_adjp[(m0 + (i >> 3)) * 32 + jc * 8 + (i & 7)];
    }

    // ---- per-thread fragment constants ----
    int gr = lane >> 2, tc = lane & 3;      // C-frag: rows gr/gr+8, cols 2tc/2tc+1
    int lrow  = lane & 15;
    int lcol8 = 8 * (lane >> 4);
    uint32_t aoffA    = (uint32_t)((16 * w + lrow) * 136 + lcol8) * 2;
    uint32_t aoffBrow = (uint32_t)(lrow * 136 + lcol8) * 2;

    wmma::fragment<wmma::accumulator, 16, 16, 16, float> oacc[4][2];
    #pragma unroll
    for (int a = 0; a < 4; a++)
        #pragma unroll
        for (int b = 0; b < 2; b++) wmma::fill_fragment(oacc[a][b], 0.0f);

    float rs0 = 0.f, rs1 = 0.f;
    const int NIT = (N_ / JC_) / 64;        // 4 j-tiles per chunk

    #pragma unroll 1
    for (int it = 0; it < NIT; it++) {
        uint32_t XJ = (it & 1) ? smXj1 : smXj0;
        __nv_bfloat16* XJp = (it & 1) ? Xj1 : Xj0;
        if (it + 1 < NIT) {
            uint32_t XJn = (it & 1) ? smXj0 : smXj1;
            int j0n = jbase + (it + 1) * 64;
            #pragma unroll
            for (int q = 0; q < 8; q++) {   // FULL 1024 uint4
                int idx = tid + q * 128;
                int r = idx >> 4, c = (idx & 15) * 8;
                cpa16(XJn + (uint32_t)(r * 136 + c) * 2, &Xt[(j0n + r) * D_ + c]);
            }
            cpa_commit();
            cpa_wait<1>();
        } else {
            cpa_wait<0>();
        }
        __syncthreads();

        // ---- QK: S(16x64) in registers ----
        float s[8][4];
        #pragma unroll
        for (int nb = 0; nb < 8; nb++)
            #pragma unroll
            for (int k = 0; k < 4; k++) s[nb][k] = 0.0f;

        #pragma unroll
        for (int ks = 0; ks < 8; ks++) {
            int k0 = ks * 16;
            uint32_t a0, a1, a2, a3;
            ldsm4(a0, a1, a2, a3, smXm + aoffA + (uint32_t)k0 * 2);
            #pragma unroll
            for (int p = 0; p < 4; p++) {
                uint32_t q0, q1, q2, q3;
                ldsm4(q0, q1, q2, q3, XJ + aoffBrow + (uint32_t)(16 * p * 136 + k0) * 2);
                mma16816(s[2 * p],     a0, a1, a2, a3, q0, q2);
                mma16816(s[2 * p + 1], a0, a1, a2, a3, q1, q3);
            }
        }

        // ---- mask + exp + rowsum; P -> smem ----
        {
            int rowE = 16 * w + gr;
            int ar0 = rowE * 8 + it * 2;
            int ar1 = (rowE + 8) * 8 + it * 2;
            unsigned w0a = adjs[ar0], w0b = adjs[ar0 + 1];
            unsigned w1a = adjs[ar1], w1b = adjs[ar1 + 1];
            #pragma unroll
            for (int nb = 0; nb < 8; nb++) {
                int col = 8 * nb + 2 * tc;
                unsigned wa = (nb < 4) ? w0a : w0b;
                unsigned wb = (nb < 4) ? w1a : w1b;
                int sh = col & 31;
                float e0 = ((wa >> sh) & 1u)       ? __expf(fminf(s[nb][0] * SCALE, 30.f)) : 0.f;
                float e1 = ((wa >> (sh + 1)) & 1u) ? __expf(fminf(s[nb][1] * SCALE, 30.f)) : 0.f;
                float f0 = ((wb >> sh) & 1u)       ? __expf(fminf(s[nb][2] * SCALE, 30.f)) : 0.f;
                float f1 = ((wb >> (sh + 1)) & 1u) ? __expf(fminf(s[nb][3] * SCALE, 30.f)) : 0.f;
                rs0 += e0 + e1;
                rs1 += f0 + f1;
                *(__nv_bfloat162*)&Pts[rowE * 72 + col]       = __floats2bfloat162_rn(e0, e1);
                *(__nv_bfloat162*)&Pts[(rowE + 8) * 72 + col] = __floats2bfloat162_rn(f0, f1);
            }
        }
        __syncthreads();

        // ---- AV: O[:, 32w:+32] += P . Xj ----
        #pragma unroll
        for (int kk = 0; kk < 4; kk++) {
            wmma::fragment<wmma::matrix_b, 16, 16, 16, __nv_bfloat16, wmma::row_major> b0, b1;
            wmma::load_matrix_sync(b0, &XJp[(kk * 16) * 136 + 32 * w], 136);
            wmma::load_matrix_sync(b1, &XJp[(kk * 16) * 136 + 32 * w + 16], 136);
            #pragma unroll
            for (int rr = 0; rr < 4; rr++) {
                wmma::fragment<wmma::matrix_a, 16, 16, 16, __nv_bfloat16, wmma::row_major> af;
                wmma::load_matrix_sync(af, &Pts[(16 * rr) * 72 + kk * 16], 72);
                wmma::mma_sync(oacc[rr][0], af, b0, oacc[rr][0]);
                wmma::mma_sync(oacc[rr][1], af, b1, oacc[rr][1]);
            }
        }
        __syncthreads();
    }

    // ---- epilogue ----
    rs0 += __shfl_xor_sync(~0u, rs0, 1); rs0 += __shfl_xor_sync(~0u, rs0, 2);
    rs1 += __shfl_xor_sync(~0u, rs1, 1); rs1 += __shfl_xor_sync(~0u, rs1, 2);
    if (tc == 0) {
        int lbase = (jc * T_ + t) * N_ + m0;
        g_lpart[lbase + 16 * w + gr]     = rs0;
        g_lpart[lbase + 16 * w + gr + 8] = rs1;
    }
    #pragma unroll
    for (int rr = 0; rr < 4; rr++)
        #pragma unroll
        for (int cc = 0; cc < 2; cc++)
            wmma::store_matrix_sync(&Osm[(16 * rr) * 132 + 32 * w + 16 * cc],
                                    oacc[rr][cc], 132, wmma::mem_row_major);
    __syncthreads();
    float* Oout = g_Opart + ((size_t)(jc * T_ + t) * N_ + m0) * D_;
    #pragma unroll
    for (int q = 0; q < 16; q++) {
        int f4 = tid + q * 128;             // 2048 float4
        int r = f4 >> 5, c4 = (f4 & 31) * 4;
        const float* src = &Osm[r * 132 + c4];
        __stcs((float4*)&Oout[r * D_ + c4], make_float4(src[0], src[1], src[2], src[3]));
    }
}

// ---------------- K2a: reduce + normalize + Gram + sigmoid -> g_SW ----------------
// 1024 blocks x 256 threads, one node per block. Small kernel; finishes fast
// so the pure-store expand kernel starts with zero serial prefix.
__global__ void __launch_bounds__(256, 4) k_sw() {
    __shared__ float ysm[T_][132];          // raw numerator sums, padded
    __shared__ float linv_s[8];             // [t]
    int tid = threadIdx.x;
    int j   = blockIdx.x;                   // node

    if (tid < 8) {
        int row = tid * N_ + j;
        float l = 0.f;
        #pragma unroll
        for (int c = 0; c < JC_; c++) l += g_lpart[c * T_ * N_ + row];
        linv_s[tid] = (l > 0.f) ? (1.0f / l) : 0.0f;   // inert guard
    }

    // 8t x 32 float4 = 256 positions; one per thread
    {
        int tt = tid >> 5, d4 = (tid & 31) * 4;
        size_t base = (((size_t)tt * N_) + j) * D_ + d4;
        float4 acc = __ldcs((const float4*)&g_Opart[base]);
        #pragma unroll
        for (int c = 1; c < JC_; c++) {
            float4 v = __ldcs((const float4*)&g_Opart[(size_t)c * T_ * N_ * D_ + base]);
            acc.x += v.x; acc.y += v.y; acc.z += v.z; acc.w += v.w;
        }
        *(float4*)&ysm[tt][d4] = acc;
    }
    __syncthreads();

    if (tid < 64) {
        int tt = tid >> 3, ss = tid & 7;
        const float* yt = ysm[tt];
        const float* ys = ysm[ss];
        float acc = 0.f;
        #pragma unroll
        for (int d4 = 0; d4 < 128; d4 += 4) {
            float4 a = *(const float4*)&yt[d4];
            float4 b = *(const float4*)&ys[d4];
            acc = fmaf(a.x, b.x, acc); acc = fmaf(a.y, b.y, acc);
            acc = fmaf(a.z, b.z, acc); acc = fmaf(a.w, b.w, acc);
        }
        float x = acc * linv_s[tt] * linv_s[ss] * SCALE;
        g_SW[j * 64 + tid] = 1.0f / (1.0f + __expf(-x));   // [j][t*8+s]
    }
}

// ---------------- K2b: pure streaming expand, one output row per block ----------------
// 8192 blocks x 256 threads. Row r = s*N + j is one contiguous 32KB stream;
// t-segments (4KB each) are consecutive. 8 STG.128 per thread, __stcs.
__global__ void __launch_bounds__(256) k_expand(float* __restrict__ out) {
    int r = blockIdx.x;                     // 0..8191
    int s = r >> 10, j = r & 1023;
    const float* sw = g_SW + j * 64 + s;    // stride 8 over t
    float4* p = (float4*)out + (size_t)r * 2048 + threadIdx.x;
    #pragma unroll
    for (int t = 0; t < T_; t++) {
        float v = __ldg(&sw[t * 8]);
        __stcs(p, make_float4(v, v, v, v));
        p += 256;
    }
}

extern "C" void kernel_launch(void* const* d_in, const int* in_sizes, int n_in,
                              void* d_out, int out_size) {
    const float* raw = (const float*)d_in[0];
    const int*   adj = (const int*)d_in[1];
    float*       out = (float*)d_out;

    static bool attr_set = false;
    if (!attr_set) {
        cudaFuncSetAttribute(k_attn, cudaFuncAttributeMaxDynamicSharedMemorySize, SM_TOT);
        attr_set = true;
    }

    k_cast<<<(T_ * N_ * D_ + 255) / 256, 256>>>(raw);
    k_pack<<<(N_ * N_) / 256, 256>>>(adj);
    k_attn<<<dim3(16, JC_, T_), 128, SM_TOT>>>();
    k_sw<<<N_, 256>>>();
    k_expand<<<T_ * N_, 256>>>(out);
}